// round 14
// baseline (speedup 1.0000x reference)
#include <cuda_runtime.h>
#include <cuda_fp16.h>
#include <cstdint>

namespace {
constexpr int B_  = 4;
constexpr int C_  = 64;
constexpr int IC_ = 16;
constexpr int D_  = 8;
constexpr int H_  = 128;
constexpr int W_  = 128;
constexpr int MID_ = 4;
constexpr int HP_ = 64;
constexpr int L_  = 4096;
constexpr int F_  = 144;    // IC*3*3 = 9 * 16
constexpr float SCALE_ = 10.0f;
constexpr float LOG2E_ = 1.4426950408889634f;

// flash smem layout (bytes), 64-row tiles, k16-tiled swizzled operands
constexpr int QTILE_B = 2048;                 // 64 rows x 32B
constexpr int VTILE_B = 4608;                 // 144 rows x 32B
constexpr int QK_PLANE = 9 * QTILE_B;         // 18432
constexpr int V_PLANE  = 4 * VTILE_B;         // 18432
constexpr int Q_OFF = 0;                      // 18432
constexpr int K_OFF = 18432;                  // 2 bufs
constexpr int V_OFF = K_OFF + 2 * QK_PLANE;   // 55296; 2 bufs
constexpr int P_OFF = V_OFF + 2 * V_PLANE;    // 92160; 4*2048 = 8192
constexpr int FLASH_SMEM = P_OFF + 8192;      // 100352
}

// ============================================================
// helpers
// ============================================================
__device__ __forceinline__ void mma16816(float* c, const uint32_t* a,
                                         uint32_t b0, uint32_t b1) {
    asm volatile(
        "mma.sync.aligned.m16n8k16.row.col.f32.f16.f16.f32 "
        "{%0,%1,%2,%3}, {%4,%5,%6,%7}, {%8,%9}, {%0,%1,%2,%3};"
        : "+f"(c[0]), "+f"(c[1]), "+f"(c[2]), "+f"(c[3])
        : "r"(a[0]), "r"(a[1]), "r"(a[2]), "r"(a[3]), "r"(b0), "r"(b1));
}

__device__ __forceinline__ void ldsm_x4(uint32_t* r, uint32_t smaddr) {
    asm volatile("ldmatrix.sync.aligned.m8n8.x4.shared.b16 {%0,%1,%2,%3}, [%4];"
                 : "=r"(r[0]), "=r"(r[1]), "=r"(r[2]), "=r"(r[3]) : "r"(smaddr));
}
__device__ __forceinline__ void ldsm_x2(uint32_t* r, uint32_t smaddr) {
    asm volatile("ldmatrix.sync.aligned.m8n8.x2.shared.b16 {%0,%1}, [%2];"
                 : "=r"(r[0]), "=r"(r[1]) : "r"(smaddr));
}

__device__ __forceinline__ void cp_async16(uint32_t smaddr, const void* gptr) {
    asm volatile("cp.async.cg.shared.global [%0], [%1], 16;"
                 :: "r"(smaddr), "l"(gptr) : "memory");
}
#define CP_COMMIT() asm volatile("cp.async.commit_group;" ::: "memory")
#define CP_WAIT(n)  asm volatile("cp.async.wait_group %0;" :: "n"(n) : "memory")

__device__ __forceinline__ uint32_t smem_u32(const void* p) {
    uint32_t a;
    asm("{ .reg .u64 t; cvta.to.shared.u64 t, %1; cvt.u32.u64 %0, t; }" : "=r"(a) : "l"(p));
    return a;
}

// XOR swizzle: bit7 -> bit4 (row-stride 32B => conflict-free LDSM phases)
__device__ __forceinline__ uint32_t swz(uint32_t o) { return o ^ ((o & 0x80u) >> 3); }

// ============================================================
// scratch (device globals)
// ============================================================
__device__ float d_conv[3][B_][IC_][H_][W_];
__device__ __align__(16) __half d_qh[B_][L_][F_];   // 10*log2e*q, fp16
__device__ __align__(16) __half d_kh[B_][L_][F_];
__device__ __align__(16) __half d_vth[B_][F_][L_];  // V transposed
__device__ float d_zi[B_][L_][F_];
__device__ __align__(16) float d_yvec[B_][C_][H_][W_];

// ============================================================
// Kernel 1: 1x1 convs at the mid depth slice only.
// ============================================================
__global__ void k_conv(const float* __restrict__ s, const float* __restrict__ g,
                       const float* __restrict__ gw, const float* __restrict__ gb,
                       const float* __restrict__ tw, const float* __restrict__ tb,
                       const float* __restrict__ pw, const float* __restrict__ pb) {
    __shared__ float wq[IC_ * C_], wv[IC_ * C_], wk[IC_ * C_];
    __shared__ float bq[IC_], bv[IC_], bk[IC_];
    const int tid = threadIdx.x;
    for (int i = tid; i < IC_ * C_; i += 128) { wq[i] = gw[i]; wv[i] = tw[i]; wk[i] = pw[i]; }
    if (tid < IC_) { bq[tid] = gb[tid]; bv[tid] = tb[tid]; bk[tid] = pb[tid]; }
    __syncthreads();

    const int y = blockIdx.x, b = blockIdx.y, x = tid;
    float aq[IC_], av[IC_], ak[IC_];
#pragma unroll
    for (int ic = 0; ic < IC_; ic++) { aq[ic] = bq[ic]; av[ic] = bv[ic]; ak[ic] = bk[ic]; }

    const size_t base = ((size_t)b * C_ * D_ + MID_) * (H_ * W_) + (size_t)y * W_ + x;
    const size_t cstride = (size_t)D_ * H_ * W_;
#pragma unroll 4
    for (int c = 0; c < C_; c++) {
        const float sv = s[base + c * cstride];
        const float gv = g[base + c * cstride];
#pragma unroll
        for (int ic = 0; ic < IC_; ic++) {
            aq[ic] += wq[ic * C_ + c] * sv;
            av[ic] += wv[ic * C_ + c] * gv;
            ak[ic] += wk[ic * C_ + c] * gv;
        }
    }
#pragma unroll
    for (int ic = 0; ic < IC_; ic++) {
        const int o = ((b * IC_ + ic) * H_ + y) * W_ + x;
        (&d_conv[0][0][0][0][0])[o] = aq[ic];
        (&d_conv[1][0][0][0][0])[o] = av[ic];
        (&d_conv[2][0][0][0][0])[o] = ak[ic];
    }
}

// ============================================================
// Kernel 2: patch extraction, locality-tiled.
// ============================================================
__global__ void k_patch() {
    __shared__ __half q_s[64][F_];
    __shared__ __half k_s[64][F_];
    const int hp = blockIdx.x, b = blockIdx.y;
    const int tid = threadIdx.x;

    for (int e = tid; e < 64 * 18; e += 128) {
        const int wp = e / 18, u = e - (e / 18) * 18;
        __half qv[8], kv[8];
#pragma unroll
        for (int j = 0; j < 8; j++) {
            const int f = u * 8 + j;
            const int c = f / 9, r = f - (f / 9) * 9;
            const int ki = r / 3, kj = r - (r / 3) * 3;
            const int y = hp * 2 - 1 + ki;
            const int x = wp * 2 - 1 + kj;
            const bool in = ((unsigned)y < (unsigned)H_) && ((unsigned)x < (unsigned)W_);
            const float q = in ? d_conv[0][b][c][y][x] : 0.0f;
            const float k = in ? d_conv[2][b][c][y][x] : 0.0f;
            qv[j] = __float2half_rn(q * (SCALE_ * LOG2E_));
            kv[j] = __float2half_rn(k);
        }
        *(uint4*)&q_s[wp][u * 8] = *(uint4*)qv;
        *(uint4*)&k_s[wp][u * 8] = *(uint4*)kv;
    }
    __syncthreads();
    for (int e = tid; e < 64 * 18; e += 128) {
        const int wp = e / 18, u = e - (e / 18) * 18;
        const int l = hp * 64 + wp;
        *(uint4*)&d_qh[b][l][u * 8] = *(const uint4*)&q_s[wp][u * 8];
        *(uint4*)&d_kh[b][l][u * 8] = *(const uint4*)&k_s[wp][u * 8];
    }
    __syncthreads();

    __half* v_s = &q_s[0][0];
    for (int e = tid; e < F_ * 8; e += 128) {
        const int f = e >> 3, u = e & 7;
        const int c = f / 9, r = f - (f / 9) * 9;
        const int ki = r / 3, kj = r - (r / 3) * 3;
        const int y = hp * 2 - 1 + ki;
        __half vv[8];
#pragma unroll
        for (int j = 0; j < 8; j++) {
            const int wp = u * 8 + j;
            const int x = wp * 2 - 1 + kj;
            const bool in = ((unsigned)y < (unsigned)H_) && ((unsigned)x < (unsigned)W_);
            vv[j] = __float2half_rn(in ? d_conv[1][b][c][y][x] : 0.0f);
        }
        *(uint4*)&v_s[f * 64 + u * 8] = *(uint4*)vv;
    }
    __syncthreads();
    for (int e = tid; e < F_ * 8; e += 128) {
        const int f = e >> 3, u = e & 7;
        *(uint4*)&d_vth[b][f][hp * 64 + u * 8] = *(const uint4*)&v_s[f * 64 + u * 8];
    }
}

// ============================================================
// Kernel 3: FUSED online-flash attention, 2 CTAs/SM.
// grid (64 row-tiles, B) = 256 CTAs, 256 threads = 8 warps.
// S-phase: 4x2 warps, 16x32 tiles on 64x64 chunks.
// PV-phase: 4x2 warps, 16x72 tiles. Same warp owns same rows in both
// phases -> alpha/l bookkeeping entirely in registers.
// ============================================================
__global__ __launch_bounds__(256, 2) void k_flash() {
    extern __shared__ char smc[];
    __shared__ float redmax[2][64];
    __shared__ float redsum[2][64];
    const uint32_t sbase = smem_u32(smc);

    const int tid = threadIdx.x;
    const int lane = tid & 31;
    const int warp = tid >> 5;
    const int wr = warp >> 1;          // 0..3 (16-row groups; same rows in S & PV)
    const int wc = warp & 1;           // 0..1 (S: 32-col halves; PV: 72-col halves)
    const int g = lane >> 2;           // 0..7
    const int t = lane & 3;            // 0..3
    const int b = blockIdx.y;
    const int row0 = blockIdx.x * 64;

    float O[9][4];
#pragma unroll
    for (int n = 0; n < 9; n++)
#pragma unroll
        for (int j = 0; j < 4; j++) O[n][j] = 0.f;

    float mrow[2] = { -1e30f, -1e30f };
    float lpart[2] = { 0.f, 0.f };
    const int rowIdx[2] = { wr * 16 + g, wr * 16 + 8 + g };

    // prologue: Q (64 rows, resident) + K chunk 0 + V chunk 0
    for (int e = tid; e < 64 * 18; e += 256) {
        const int r = e / 18, u = e - (e / 18) * 18;
        const int k16 = u >> 1, h = u & 1;
        const uint32_t o = (uint32_t)k16 * QTILE_B + swz((uint32_t)(r * 32 + h * 16));
        const int fc = k16 * 16 + h * 8;
        cp_async16(sbase + Q_OFF + o, &d_qh[b][row0 + r][fc]);
        cp_async16(sbase + K_OFF + o, &d_kh[b][r][fc]);
    }
    for (int e = tid; e < 144 * 8; e += 256) {
        const int f = e >> 3, u = e & 7;
        const int k16 = u >> 1, h = u & 1;
        const uint32_t o = (uint32_t)k16 * VTILE_B + swz((uint32_t)(f * 32 + h * 16));
        cp_async16(sbase + V_OFF + o, &d_vth[b][f][k16 * 16 + h * 8]);
    }
    CP_COMMIT();

    // LDSM lane offsets
    const uint32_t aoffS = swz((uint32_t)((wr * 16 + (lane & 15)) * 32 + ((lane >> 4) & 1) * 16));
    uint32_t boffS[2];
#pragma unroll
    for (int j = 0; j < 2; j++)
        boffS[j] = swz((uint32_t)((wc * 32 + j * 16 + (lane & 7) + ((lane >> 4) << 3)) * 32 +
                                  (((lane >> 3) & 1) << 4)));
    const uint32_t aoffP = aoffS;   // same row group, same layout (P tiles 64 rows)
    uint32_t boffV[4];
#pragma unroll
    for (int p = 0; p < 4; p++)
        boffV[p] = swz((uint32_t)((wc * 72 + p * 16 + (lane & 7) + ((lane >> 4) << 3)) * 32 +
                                  (((lane >> 3) & 1) << 4)));
    const uint32_t boffV2 = swz((uint32_t)((wc * 72 + 64 + (lane & 7)) * 32 +
                                           (((lane >> 3) & 1) << 4)));

    const uint32_t Qb = sbase + Q_OFF;
    const uint32_t Pb = sbase + P_OFF;

    for (int ct = 0; ct < 64; ct++) {
        const int buf = ct & 1;
        CP_WAIT(0);
        __syncthreads();   // (C) K/V[buf] ready; prior P consumed

        // issue next K/V chunk into other buffer
        if (ct < 63) {
            const int c1 = (ct + 1) * 64;
            const uint32_t kb1 = sbase + K_OFF + (uint32_t)(buf ^ 1) * QK_PLANE;
            const uint32_t vb1 = sbase + V_OFF + (uint32_t)(buf ^ 1) * V_PLANE;
            for (int e = tid; e < 64 * 18; e += 256) {
                const int r = e / 18, u = e - (e / 18) * 18;
                const int k16 = u >> 1, h = u & 1;
                const uint32_t o = (uint32_t)k16 * QTILE_B + swz((uint32_t)(r * 32 + h * 16));
                cp_async16(kb1 + o, &d_kh[b][c1 + r][k16 * 16 + h * 8]);
            }
            for (int e = tid; e < 144 * 8; e += 256) {
                const int f = e >> 3, u = e & 7;
                const int k16 = u >> 1, h = u & 1;
                const uint32_t o = (uint32_t)k16 * VTILE_B + swz((uint32_t)(f * 32 + h * 16));
                cp_async16(vb1 + o, &d_vth[b][f][c1 + k16 * 16 + h * 8]);
            }
            CP_COMMIT();
        }

        const uint32_t Kb = sbase + K_OFF + (uint32_t)buf * QK_PLANE;
        const uint32_t Vb = sbase + V_OFF + (uint32_t)buf * V_PLANE;

        // ---- S = Q' K^T (16x32 warp tile, base-2 logits) ----
        float acc[4][4];
#pragma unroll
        for (int n = 0; n < 4; n++)
#pragma unroll
            for (int j = 0; j < 4; j++) acc[n][j] = 0.f;

#pragma unroll
        for (int k16 = 0; k16 < 9; k16++) {
            const uint32_t tb = (uint32_t)k16 * QTILE_B;
            uint32_t a[4], b0[4], b1[4];
            ldsm_x4(a, Qb + tb + aoffS);
            ldsm_x4(b0, Kb + tb + boffS[0]);
            ldsm_x4(b1, Kb + tb + boffS[1]);
            mma16816(acc[0], a, b0[0], b0[1]);
            mma16816(acc[1], a, b0[2], b0[3]);
            mma16816(acc[2], a, b1[0], b1[1]);
            mma16816(acc[3], a, b1[2], b1[3]);
        }

        // ---- warp-local row max into redmax ----
#pragma unroll
        for (int ri = 0; ri < 2; ri++) {
            const int jb = ri * 2;
            float mx = acc[0][jb];
#pragma unroll
            for (int n = 0; n < 4; n++)
                mx = fmaxf(mx, fmaxf(acc[n][jb], acc[n][jb + 1]));
            mx = fmaxf(mx, __shfl_xor_sync(0xffffffffu, mx, 1));
            mx = fmaxf(mx, __shfl_xor_sync(0xffffffffu, mx, 2));
            if (t == 0) redmax[wc][rowIdx[ri]] = mx;
        }
        __syncthreads();   // (A)

        // ---- P = exp2(S - m); per-thread alpha/l; O rescale ----
        float alpha[2];
#pragma unroll
        for (int ri = 0; ri < 2; ri++) {
            const int jb = ri * 2;
            const int row = rowIdx[ri];
            const float mnew = fmaxf(mrow[ri],
                                     fmaxf(redmax[0][row], redmax[1][row]));
            alpha[ri] = exp2f(mrow[ri] - mnew);
            mrow[ri] = mnew;
            float sum = 0.f;
#pragma unroll
            for (int n = 0; n < 4; n++) {
                const float e0 = exp2f(acc[n][jb] - mnew);
                const float e1 = exp2f(acc[n][jb + 1] - mnew);
                sum += e0 + e1;
                const int col = wc * 32 + n * 8 + t * 2;
                const uint32_t off = (uint32_t)(col >> 4) * QTILE_B +
                                     swz((uint32_t)(row * 32 + (col & 15) * 2));
                *(__half2*)(smc + P_OFF + off) = __floats2half2_rn(e0, e1);
            }
            sum += __shfl_xor_sync(0xffffffffu, sum, 1);
            sum += __shfl_xor_sync(0xffffffffu, sum, 2);
            lpart[ri] = lpart[ri] * alpha[ri] + sum;
        }
#pragma unroll
        for (int n = 0; n < 9; n++) {
            O[n][0] *= alpha[0]; O[n][1] *= alpha[0];
            O[n][2] *= alpha[1]; O[n][3] *= alpha[1];
        }
        __syncthreads();   // (B) P ready

        // ---- O += P V (4 k16; warp tile 16x72) ----
#pragma unroll
        for (int k16 = 0; k16 < 4; k16++) {
            const uint32_t ptb = Pb + (uint32_t)k16 * QTILE_B;
            const uint32_t vtb = Vb + (uint32_t)k16 * VTILE_B;
            uint32_t a[4];
            ldsm_x4(a, ptb + aoffP);
#pragma unroll
            for (int p = 0; p < 4; p++) {
                uint32_t bb[4];
                ldsm_x4(bb, vtb + boffV[p]);
                mma16816(O[2 * p],     a, bb[0], bb[1]);
                mma16816(O[2 * p + 1], a, bb[2], bb[3]);
            }
            {
                uint32_t bs[2];
                ldsm_x2(bs, vtb + boffV2);
                mma16816(O[8], a, bs[0], bs[1]);
            }
        }
    }

    // final: combine lpart across the two wc halves, normalize, store
    if (t == 0) {
        redsum[wc][rowIdx[0]] = lpart[0];
        redsum[wc][rowIdx[1]] = lpart[1];
    }
    __syncthreads();
    {
        const float liA = 1.0f / (redsum[0][rowIdx[0]] + redsum[1][rowIdx[0]]);
        const float liB = 1.0f / (redsum[0][rowIdx[1]] + redsum[1][rowIdx[1]]);
#pragma unroll
        for (int n = 0; n < 9; n++) {
            const int col = wc * 72 + n * 8 + t * 2;
            *(float2*)&d_zi[b][row0 + rowIdx[0]][col] = make_float2(O[n][0] * liA, O[n][1] * liA);
            *(float2*)&d_zi[b][row0 + rowIdx[1]][col] = make_float2(O[n][2] * liB, O[n][3] * liB);
        }
    }
}

// ============================================================
// Kernel 4: fold (overlap-add + count normalize) + W_w conv -> yvec
// ============================================================
__global__ void k_fold(const float* __restrict__ Wmat, const float* __restrict__ Wb) {
    __shared__ float zs[IC_][W_];
    __shared__ float wsm[C_ * IC_];
    __shared__ float bsm[C_];
    const int x = threadIdx.x;
    const int y = blockIdx.x, b = blockIdx.y;
    for (int i = x; i < C_ * IC_; i += 128) wsm[i] = Wmat[i];
    if (x < C_) bsm[x] = Wb[x];

    float v[IC_];
#pragma unroll
    for (int ic = 0; ic < IC_; ic++) v[ic] = 0.f;
    int cnt = 0;
#pragma unroll
    for (int i = 0; i < 3; i++) {
        const int tY = y + 1 - i;
        if (tY < 0 || (tY & 1) || (tY >> 1) >= HP_) continue;
        const int hp = tY >> 1;
#pragma unroll
        for (int j = 0; j < 3; j++) {
            const int tX = x + 1 - j;
            if (tX < 0 || (tX & 1) || (tX >> 1) >= HP_) continue;
            const int wp = tX >> 1;
            const float* zrow = &d_zi[b][hp * 64 + wp][0];
            cnt++;
#pragma unroll
            for (int ic = 0; ic < IC_; ic++) v[ic] += zrow[ic * 9 + i * 3 + j];
        }
    }
    const float invc = 1.0f / (float)cnt;
#pragma unroll
    for (int ic = 0; ic < IC_; ic++) zs[ic][x] = v[ic] * invc;
    __syncthreads();

    for (int o = 0; o < C_; o++) {
        float a = bsm[o];
#pragma unroll
        for (int ic = 0; ic < IC_; ic++) a += wsm[o * IC_ + ic] * zs[ic][x];
        d_yvec[b][o][y][x] = a;
    }
}

// ============================================================
// Kernel 5: out = s + yvec (broadcast over D), float4 streaming.
// ============================================================
__global__ void k_out(const float4* __restrict__ s4, float4* __restrict__ out4) {
    const int idx = blockIdx.x * 256 + threadIdx.x;
    const int pix4 = idx & 4095;
    const int bo = (idx >> 12) >> 3;
    const float4 sv = s4[idx];
    const float4 yv = ((const float4*)&d_yvec[0][0][0][0])[bo * 4096 + pix4];
    out4[idx] = make_float4(sv.x + yv.x, sv.y + yv.y, sv.z + yv.z, sv.w + yv.w);
}

// ============================================================
extern "C" void kernel_launch(void* const* d_in, const int* /*in_sizes*/, int /*n_in*/,
                              void* d_out, int /*out_size*/) {
    const float* s   = (const float*)d_in[0];
    const float* g   = (const float*)d_in[1];
    const float* g_w = (const float*)d_in[2];
    const float* g_b = (const float*)d_in[3];
    const float* t_w = (const float*)d_in[4];
    const float* t_b = (const float*)d_in[5];
    const float* p_w = (const float*)d_in[6];
    const float* p_b = (const float*)d_in[7];
    const float* W_w = (const float*)d_in[8];
    const float* W_b = (const float*)d_in[9];
    float* out = (float*)d_out;

    cudaFuncSetAttribute(k_flash, cudaFuncAttributeMaxDynamicSharedMemorySize, FLASH_SMEM);

    k_conv<<<dim3(H_, B_), 128>>>(s, g, g_w, g_b, t_w, t_b, p_w, p_b);
    k_patch<<<dim3(HP_, B_), 128>>>();

    k_flash<<<dim3(64, B_), 256, FLASH_SMEM>>>();

    k_fold<<<dim3(H_, B_), 128>>>(W_w, W_b);

    const int total4 = (B_ * C_ * D_ * H_ * W_) / 4;
    k_out<<<total4 / 256, 256>>>((const float4*)s, (float4*)out);
}